// round 6
// baseline (speedup 1.0000x reference)
#include <cuda_runtime.h>

// LogLinearAttention — algebraic collapse (exact; rel_err=0 across R1-R4):
//   softmax over axis=1 then sum over axis=1 => attention columns sum to 1:
//     out[b] = sigmoid( xsum[b,:]·c + S*(br·Wl) + bl )
//   xsum[b,e] = sum_s x[b,s,e],  c[e] = sum_d Wl[d]*Wr[d,e].
//
// R5: kill the serial k_c (4.6us of latency-exposed 1MB read blocking the
// x pass). The x stream doesn't need c — compute partial xsum vectors and
// fold c partials in the SAME fused grid (concurrent), then a one-wave dot
// kernel + trivial finisher.

#define BB 8
#define SS 2048
#define DD 512
#define DD4 (DD / 4)              // 128 float4 columns
#define JPB 32                    // xsum blocks per batch
#define NXB (BB * JPB)            // 256 xsum blocks
#define ROWS_PER (SS / JPB)       // 64 rows per block
#define CBLK_D 16                 // d-chunks for c partials
#define CBLK_E 8                  // e-chunks for c partials
#define DCH (DD / CBLK_D)         // 32 d rows per c-chunk
#define ECH4 (DD4 / CBLK_E)       // 16 float4 cols per c-chunk
#define NCB (CBLK_D * CBLK_E)     // 128 c blocks
#define DPB 16                    // dot blocks per batch
#define VPD (JPB / DPB)           // 2 partial vectors per dot block

__device__ float g_xp[NXB * DD];        // per-block partial xsum vectors (512 KB)
__device__ float g_cpart[CBLK_D * DD];  // c partials over d-chunks (32 KB)
__device__ float g_dots[BB * DPB];      // per-block partial dot scalars

// ── K1: 256 streaming xsum blocks + 128 c-partial blocks, one grid ──
__global__ void __launch_bounds__(256) k_stream(
    const float* __restrict__ x,
    const float* __restrict__ Wr,
    const float* __restrict__ Wl)
{
    const int blk = blockIdx.x;
    const int tid = threadIdx.x;

    if (blk < NXB) {
        // partial xsum over 64 rows; thread = (r0 = tid>>7, col = tid&127)
        const int b   = blk / JPB;
        const int j   = blk % JPB;
        const int col = tid & (DD4 - 1);
        const int r0  = tid >> 7;                  // 0 or 1

        const float4* xb =
            reinterpret_cast<const float4*>(x + ((size_t)b * SS + (size_t)j * ROWS_PER) * DD);
        float4 acc = make_float4(0.f, 0.f, 0.f, 0.f);
#pragma unroll 4
        for (int r = r0; r < ROWS_PER; r += 2) {   // continuous stream, MLP_p1 ~ 4
            float4 v = xb[(size_t)r * DD4 + col];
            acc.x += v.x; acc.y += v.y; acc.z += v.z; acc.w += v.w;
        }

        // combine the two row-phases via shared, thread pair (r0=0,1) same col
        __shared__ float4 s_half[DD4];
        if (r0 == 1) s_half[col] = acc;
        __syncthreads();
        if (r0 == 0) {
            float4 o = s_half[col];
            acc.x += o.x; acc.y += o.y; acc.z += o.z; acc.w += o.w;
            reinterpret_cast<float4*>(g_xp + (size_t)blk * DD)[col] = acc;
        }
    } else {
        // c partial: cpart[jd][e] = sum_{d in chunk jd} Wl[d]*Wr[d,e]
        const int cb = blk - NXB;                  // 0..127
        const int jd = cb / CBLK_E;
        const int je = cb % CBLK_E;
        const int tf = tid % ECH4;                 // float4 col in chunk (0..15)
        const int td = tid / ECH4;                 // d-subgroup (0..15), 2 d's each

        const int e4 = je * ECH4 + tf;
        float4 acc = make_float4(0.f, 0.f, 0.f, 0.f);
#pragma unroll
        for (int k = 0; k < DCH / 16; ++k) {       // 2 d rows per thread
            const int d = jd * DCH + td * (DCH / 16) + k;
            const float wl = __ldg(&Wl[d]);
            const float4 w = reinterpret_cast<const float4*>(Wr)[(size_t)d * DD4 + e4];
            acc.x += wl * w.x; acc.y += wl * w.y; acc.z += wl * w.z; acc.w += wl * w.w;
        }

        __shared__ float4 s_acc[16][ECH4];
        s_acc[td][tf] = acc;
        __syncthreads();
        if (td == 0) {
            float4 t = s_acc[0][tf];
#pragma unroll
            for (int i = 1; i < 16; ++i) {
                float4 v = s_acc[i][tf];
                t.x += v.x; t.y += v.y; t.z += v.z; t.w += v.w;
            }
            reinterpret_cast<float4*>(g_cpart)[(size_t)jd * DD4 + e4] = t;
        }
    }
}

// ── K2: 128 one-wave blocks: fold 2 xsum partials + fold c, dot → scalar ──
__global__ void __launch_bounds__(128) k_dot()
{
    const int b   = blockIdx.x / DPB;
    const int i   = blockIdx.x % DPB;
    const int tid = threadIdx.x;               // one float4 column each

    float4 acc = make_float4(0.f, 0.f, 0.f, 0.f);
    const float4* pp =
        reinterpret_cast<const float4*>(g_xp + ((size_t)b * JPB + i * VPD) * DD) + tid;
#pragma unroll
    for (int p = 0; p < VPD; ++p) {
        float4 v = pp[(size_t)p * DD4];
        acc.x += v.x; acc.y += v.y; acc.z += v.z; acc.w += v.w;
    }

    float4 c4 = make_float4(0.f, 0.f, 0.f, 0.f);
#pragma unroll
    for (int jd = 0; jd < CBLK_D; ++jd) {
        float4 v = reinterpret_cast<const float4*>(g_cpart)[(size_t)jd * DD4 + tid];
        c4.x += v.x; c4.y += v.y; c4.z += v.z; c4.w += v.w;
    }

    float val = acc.x * c4.x + acc.y * c4.y + acc.z * c4.z + acc.w * c4.w;
#pragma unroll
    for (int off = 16; off > 0; off >>= 1)
        val += __shfl_down_sync(0xffffffffu, val, off);
    __shared__ float warp_s[4];
    if ((tid & 31) == 0) warp_s[tid >> 5] = val;
    __syncthreads();
    if (tid == 0)
        g_dots[blockIdx.x] = warp_s[0] + warp_s[1] + warp_s[2] + warp_s[3];
}

// ── K3: fold 16 dot scalars per batch + bias term, sigmoid ──
__global__ void __launch_bounds__(128) k_final(
    const float* __restrict__ br,
    const float* __restrict__ Wl,
    const float* __restrict__ bl,
    float* __restrict__ out)
{
    const int tid = threadIdx.x;
    __shared__ float warp_s[4];
    __shared__ float s_bias;

    // bias dot br·Wl over 512 elems (float4 per thread)
    const float4 br4 = reinterpret_cast<const float4*>(br)[tid];
    const float4 wl4 = reinterpret_cast<const float4*>(Wl)[tid];
    float bv = br4.x * wl4.x + br4.y * wl4.y + br4.z * wl4.z + br4.w * wl4.w;
#pragma unroll
    for (int off = 16; off > 0; off >>= 1)
        bv += __shfl_down_sync(0xffffffffu, bv, off);
    if ((tid & 31) == 0) warp_s[tid >> 5] = bv;
    __syncthreads();
    if (tid == 0) s_bias = warp_s[0] + warp_s[1] + warp_s[2] + warp_s[3];
    __syncthreads();

    // fold 16 scalars per batch: tid -> (b = tid>>4, i = tid&15), warp-local
    float d = g_dots[tid];                     // BB*DPB = 128 scalars
#pragma unroll
    for (int off = 8; off > 0; off >>= 1)
        d += __shfl_down_sync(0xffffffffu, d, off, 16);
    if ((tid & 15) == 0) {
        const int b = tid >> 4;
        float z = d + (float)SS * s_bias + bl[0];
        out[b] = 1.0f / (1.0f + expf(-z));
    }
}

extern "C" void kernel_launch(void* const* d_in, const int* in_sizes, int n_in,
                              void* d_out, int out_size)
{
    // metadata order: x, Wq, bq, Wv, bv, Wr, br, Wl, bl
    const float* x  = (const float*)d_in[0];
    const float* Wr = (const float*)d_in[5];
    const float* br = (const float*)d_in[6];
    const float* Wl = (const float*)d_in[7];
    const float* bl = (const float*)d_in[8];
    float* out = (float*)d_out;

    k_stream<<<NXB + NCB, 256>>>(x, Wr, Wl);
    k_dot<<<BB * DPB, 128>>>();
    k_final<<<1, 128>>>(br, Wl, bl, out);
}

// round 7
// speedup vs baseline: 1.3233x; 1.3233x over previous
#include <cuda_runtime.h>

// LogLinearAttention — algebraic collapse (exact; rel_err=0 across all rounds):
//   softmax over axis=1 then sum over axis=1 => attention columns sum to 1:
//     out[b] = sigmoid( sum_{s,e} x[b,s,e]*c[e] + S*(br·Wl) + bl )
//   c[e] = sum_d Wl[d]*Wr[d,e].  q/v projections are dead.
//
// R6: revert to the measured-best 12.77us structure (k_c -> k_main direct dot
// -> k_final); k_main/k_final UNCHANGED. Only change: k_c rebuilt for max
// parallelism (256 blocks x 256 thr, one float4 load per thread, tree reduce)
// to cut its 4.6us latency exposure to ~1.2us.

#define BB 8
#define SS 2048
#define DD 512
#define DD4 (DD / 4)              // 128 float4 columns
#define CBLK_D 16                 // d-chunks for c partials
#define CBLK_E 16                 // e-chunks for c partials
#define DCH (DD / CBLK_D)         // 32 d rows per chunk
#define ECH4 (DD4 / CBLK_E)       // 8 float4 cols per chunk
#define JPB 37                    // row-range blocks per batch (8*37=296 = 2*148)
#define NBLK (BB * JPB)           // 296 main blocks

__device__ float g_cpart[CBLK_D * DD];  // c partials over d-chunks (32 KB)
__device__ float g_dots[NBLK];          // per-block partial dots

// ── k_c: 256 blocks x 256 threads; ONE float4 load per thread, tree reduce ──
//    block (jd, je): d rows [jd*32, jd*32+32), float4 cols [je*8, je*8+8)
__global__ void __launch_bounds__(256) k_c(
    const float* __restrict__ Wr,
    const float* __restrict__ Wl)
{
    const int jd = blockIdx.x >> 4;           // d-chunk 0..15
    const int je = blockIdx.x & 15;           // e-chunk 0..15
    const int td = threadIdx.x >> 3;          // d row in chunk 0..31
    const int tf = threadIdx.x & 7;           // float4 col in chunk 0..7

    const int d  = jd * DCH + td;
    const int e4 = je * ECH4 + tf;

    const float  wl = __ldg(&Wl[d]);
    const float4 w  = reinterpret_cast<const float4*>(Wr)[(size_t)d * DD4 + e4];

    __shared__ float4 s[DCH][ECH4];           // 4 KB
    s[td][tf] = make_float4(wl * w.x, wl * w.y, wl * w.z, wl * w.w);
    __syncthreads();

#pragma unroll
    for (int off = DCH / 2; off > 0; off >>= 1) {
        if (td < off) {
            float4 a = s[td][tf], bq = s[td + off][tf];
            s[td][tf] = make_float4(a.x + bq.x, a.y + bq.y, a.z + bq.z, a.w + bq.w);
        }
        __syncthreads();
    }
    if (td == 0)
        reinterpret_cast<float4*>(g_cpart)[(size_t)jd * DD4 + e4] = s[0][tf];
}

// ── k_main: UNCHANGED from the 12.77us best. 296 blocks x 256 thr; each block
//    streams its row range of x and accumulates the scalar dot with c.
__global__ void __launch_bounds__(256) k_main(
    const float* __restrict__ x)
{
    const int blk = blockIdx.x;
    const int b   = blk / JPB;
    const int j   = blk % JPB;
    const int tid = threadIdx.x;
    const int col = tid & (DD4 - 1);          // float4 column 0..127
    const int r0  = tid >> 7;                 // 0 or 1

    // fold this column's c from the 16 d-chunk partials (L2-hot, 16 loads)
    float4 c4 = make_float4(0.f, 0.f, 0.f, 0.f);
#pragma unroll
    for (int jd = 0; jd < CBLK_D; ++jd) {
        float4 v = reinterpret_cast<const float4*>(g_cpart)[(size_t)jd * DD4 + col];
        c4.x += v.x; c4.y += v.y; c4.z += v.z; c4.w += v.w;
    }

    const int r_begin = (j * SS) / JPB;
    const int r_end   = ((j + 1) * SS) / JPB;
    const float4* xb  = reinterpret_cast<const float4*>(x + (size_t)b * SS * DD);

    float val = 0.f;
    int r = r_begin + r0;
#pragma unroll 4
    for (; r < r_end; r += 2) {               // continuous stream, MLP_p1 ~ 4
        float4 v = xb[(size_t)r * DD4 + col];
        val += v.x * c4.x + v.y * c4.y + v.z * c4.z + v.w * c4.w;
    }

    // block-reduce 256 scalars
#pragma unroll
    for (int off = 16; off > 0; off >>= 1)
        val += __shfl_down_sync(0xffffffffu, val, off);
    __shared__ float warp_s[8];
    if ((tid & 31) == 0) warp_s[tid >> 5] = val;
    __syncthreads();
    if (tid == 0) {
        float t = warp_s[0];
#pragma unroll
        for (int i = 1; i < 8; ++i) t += warp_s[i];
        g_dots[blk] = t;
    }
}

// ── k_final: UNCHANGED. Fold 37 partial dots per batch + bias term, sigmoid ──
__global__ void __launch_bounds__(512) k_final(
    const float* __restrict__ br,
    const float* __restrict__ Wl,
    const float* __restrict__ bl,
    float* __restrict__ out)
{
    const int tid = threadIdx.x;
    __shared__ float warp_s[16];
    __shared__ float s_bias;

    // bias dot br·Wl over 512 elems: threads 0..127, float4 each
    if (tid < 128) {
        const float4 br4 = reinterpret_cast<const float4*>(br)[tid];
        const float4 wl4 = reinterpret_cast<const float4*>(Wl)[tid];
        float bv = br4.x * wl4.x + br4.y * wl4.y + br4.z * wl4.z + br4.w * wl4.w;
#pragma unroll
        for (int off = 16; off > 0; off >>= 1)
            bv += __shfl_down_sync(0xffffffffu, bv, off);
        if ((tid & 31) == 0) warp_s[tid >> 5] = bv;
    }
    __syncthreads();
    if (tid == 0) s_bias = warp_s[0] + warp_s[1] + warp_s[2] + warp_s[3];
    __syncthreads();

    // per-b fold: 64-thread group per batch, i<37 valid
    const int b = tid >> 6;
    const int i = tid & 63;
    float d = (i < JPB) ? g_dots[b * JPB + i] : 0.f;
#pragma unroll
    for (int off = 16; off > 0; off >>= 1)
        d += __shfl_down_sync(0xffffffffu, d, off);
    __shared__ float half_s[16];                 // two warps per group
    if ((tid & 31) == 0) half_s[tid >> 5] = d;
    __syncthreads();
    if (i == 0) {
        float z = half_s[(tid >> 5)] + half_s[(tid >> 5) + 1] + (float)SS * s_bias + bl[0];
        out[b] = 1.0f / (1.0f + expf(-z));
    }
}

extern "C" void kernel_launch(void* const* d_in, const int* in_sizes, int n_in,
                              void* d_out, int out_size)
{
    // metadata order: x, Wq, bq, Wv, bv, Wr, br, Wl, bl
    const float* x  = (const float*)d_in[0];
    const float* Wr = (const float*)d_in[5];
    const float* br = (const float*)d_in[6];
    const float* Wl = (const float*)d_in[7];
    const float* bl = (const float*)d_in[8];
    float* out = (float*)d_out;

    k_c<<<CBLK_D * CBLK_E, 256>>>(Wr, Wl);
    k_main<<<NBLK, 256>>>(x);
    k_final<<<1, 512>>>(br, Wl, bl, out);
}